// round 1
// baseline (speedup 1.0000x reference)
#include <cuda_runtime.h>

#define N_NODES 50000
#define N_EDGES 600000
#define HID 128
#define NG 512
#define EPS 1e-5f

// ---------------- device scratch (no allocations allowed) ----------------
__device__ float g_buf0[N_NODES * HID];   // h
__device__ float g_buf1[N_NODES * HID];   // prop output
__device__ float g_buf2[N_NODES * HID];   // gemm output
__device__ float g_buf3[N_NODES * HID];   // h0 (APPNP anchor)
__device__ int   g_deg[N_NODES];
__device__ float g_dinv[N_NODES];
__device__ int   g_rowptr[N_NODES + 1];
__device__ int   g_cursor[N_NODES];
__device__ int   g_csrc[N_EDGES];
__device__ float g_cw[N_EDGES];
__device__ float g_vn[NG * HID];
__device__ float g_vt[NG * HID];
__device__ float g_z[NG * 2 * HID];
__device__ float g_t[NG * HID];
__device__ float g_pool[NG * HID];
__device__ float g_cnt[NG];
__device__ float g_colsum[512];           // [0..256) sum, [256..512) sumsq
__device__ float g_mean[256];
__device__ float g_rstd[256];

// ---------------- setup kernels ----------------
__global__ void k_init(const float* __restrict__ vn_emb) {
    int i = blockIdx.x * blockDim.x + threadIdx.x;
    if (i < N_NODES) g_deg[i] = 0;
    if (i < NG * HID) { g_vn[i] = vn_emb[i & (HID - 1)]; g_pool[i] = 0.f; }
    if (i < NG) g_cnt[i] = 0.f;
}

__global__ void k_hist(const int* __restrict__ dst) {
    int e = blockIdx.x * blockDim.x + threadIdx.x;
    if (e < N_EDGES) atomicAdd(&g_deg[dst[e]], 1);
}

__global__ void k_dinv() {
    int i = blockIdx.x * blockDim.x + threadIdx.x;
    if (i < N_NODES) g_dinv[i] = rsqrtf((float)(g_deg[i] + 1));
}

// single-block exclusive scan of g_deg -> g_rowptr / g_cursor
__global__ void k_scan() {
    __shared__ int wsum[32];
    __shared__ int btot;
    __shared__ int sbase;
    int tid = threadIdx.x;
    if (tid == 0) sbase = 0;
    __syncthreads();
    for (int base = 0; base < N_NODES; base += 1024) {
        int i = base + tid;
        int v = (i < N_NODES) ? g_deg[i] : 0;
        int x = v;
        #pragma unroll
        for (int o = 1; o < 32; o <<= 1) {
            int y = __shfl_up_sync(0xffffffffu, x, o);
            if ((tid & 31) >= o) x += y;
        }
        if ((tid & 31) == 31) wsum[tid >> 5] = x;
        __syncthreads();
        if (tid < 32) {
            int s = wsum[tid];
            int z = s;
            #pragma unroll
            for (int o = 1; o < 32; o <<= 1) {
                int y = __shfl_up_sync(0xffffffffu, z, o);
                if (tid >= o) z += y;
            }
            wsum[tid] = z - s;
            if (tid == 31) btot = z;
        }
        __syncthreads();
        int excl = sbase + x - v + wsum[tid >> 5];
        if (i < N_NODES) { g_rowptr[i] = excl; g_cursor[i] = excl; }
        __syncthreads();
        if (tid == 0) sbase += btot;
        __syncthreads();
    }
    if (tid == 0) g_rowptr[N_NODES] = sbase;
}

__global__ void k_fill(const int* __restrict__ src, const int* __restrict__ dst) {
    int e = blockIdx.x * blockDim.x + threadIdx.x;
    if (e >= N_EDGES) return;
    int d = dst[e], s = src[e];
    int pos = atomicAdd(&g_cursor[d], 1);
    g_csrc[pos] = s;
    g_cw[pos] = g_dinv[s] * g_dinv[d];
}

// ---------------- propagation: out[v] = a * (A_hat @ in)[v] + bm * mix[v] ----------------
__global__ void k_prop(const float4* __restrict__ in, float4* __restrict__ out,
                       const float4* __restrict__ mix, float a, float bm) {
    int warp = (blockIdx.x * blockDim.x + threadIdx.x) >> 5;
    if (warp >= N_NODES) return;
    int lane = threadIdx.x & 31;
    float dv = g_dinv[warp];
    float w0 = dv * dv;
    float4 p = in[warp * 32 + lane];
    float4 acc = make_float4(w0 * p.x, w0 * p.y, w0 * p.z, w0 * p.w);
    int e = g_rowptr[warp], end = g_rowptr[warp + 1];
    for (; e < end; ++e) {
        int s = __ldg(&g_csrc[e]);
        float wv = __ldg(&g_cw[e]);
        float4 q = in[s * 32 + lane];
        acc.x = fmaf(wv, q.x, acc.x);
        acc.y = fmaf(wv, q.y, acc.y);
        acc.z = fmaf(wv, q.z, acc.z);
        acc.w = fmaf(wv, q.w, acc.w);
    }
    float4 o;
    if (bm != 0.f) {
        float4 m = mix[warp * 32 + lane];
        o = make_float4(fmaf(a, acc.x, bm * m.x), fmaf(a, acc.y, bm * m.y),
                        fmaf(a, acc.z, bm * m.z), fmaf(a, acc.w, bm * m.w));
    } else {
        o = make_float4(a * acc.x, a * acc.y, a * acc.z, a * acc.w);
    }
    out[warp * 32 + lane] = o;
}

// ---------------- big GEMM: C[nrows x 128] = A[nrows x 128] @ W[128 x 128] + bias ----------------
__global__ void gemm_big(const float* __restrict__ A, const float* __restrict__ Wg,
                         const float* __restrict__ bias, float* __restrict__ C, int nrows) {
    extern __shared__ float sh[];
    float* Ws = sh;             // 128*128
    float* As = sh + 128 * 128; // 64*16
    int tid = threadIdx.x;
    for (int i = tid; i < 128 * 128; i += 256) Ws[i] = Wg[i];
    int r0 = blockIdx.x * 64;
    int lane = tid & 31, w = tid >> 5;
    float4 acc[8];
    #pragma unroll
    for (int i = 0; i < 8; i++) acc[i] = make_float4(0.f, 0.f, 0.f, 0.f);
    for (int k0 = 0; k0 < 128; k0 += 16) {
        __syncthreads();
        for (int i = tid; i < 64 * 16; i += 256) {
            int rr = i >> 4, kk = i & 15;
            int r = r0 + rr;
            As[rr * 16 + kk] = (r < nrows) ? A[r * 128 + k0 + kk] : 0.f;
        }
        __syncthreads();
        #pragma unroll
        for (int k = 0; k < 16; k++) {
            float4 wv = *(const float4*)&Ws[(k0 + k) * 128 + lane * 4];
            #pragma unroll
            for (int i = 0; i < 8; i++) {
                float av = As[(w * 8 + i) * 16 + k];
                acc[i].x = fmaf(av, wv.x, acc[i].x);
                acc[i].y = fmaf(av, wv.y, acc[i].y);
                acc[i].z = fmaf(av, wv.z, acc[i].z);
                acc[i].w = fmaf(av, wv.w, acc[i].w);
            }
        }
    }
    float4 bv = *(const float4*)&bias[lane * 4];
    #pragma unroll
    for (int i = 0; i < 8; i++) {
        int r = r0 + w * 8 + i;
        if (r < nrows) {
            float4 o = make_float4(acc[i].x + bv.x, acc[i].y + bv.y,
                                   acc[i].z + bv.z, acc[i].w + bv.w);
            *(float4*)&C[r * 128 + lane * 4] = o;
        }
    }
}

// ---------------- batchnorm helpers ----------------
__global__ void bn_zero() {
    if (threadIdx.x < 512) g_colsum[threadIdx.x] = 0.f;
}

__global__ void bn_stats(const float* __restrict__ x, int nrows, int C) {
    int c = threadIdx.x;
    float s = 0.f, q = 0.f;
    for (int r = blockIdx.x; r < nrows; r += gridDim.x) {
        float v = x[r * C + c];
        s += v;
        q += v * v;
    }
    atomicAdd(&g_colsum[c], s);
    atomicAdd(&g_colsum[256 + c], q);
}

__global__ void bn_fin(float inv_n) {
    int c = threadIdx.x;
    float m = g_colsum[c] * inv_n;
    float var = g_colsum[256 + c] * inv_n - m * m;
    g_mean[c] = m;
    g_rstd[c] = rsqrtf(var + EPS);
}

__global__ void vt_init() {
    int i = blockIdx.x * blockDim.x + threadIdx.x;
    if (i < NG * HID) g_vt[i] = g_vn[i];
}

// big BN apply: h = relu(bn(x)) + vn[batch];  vt[batch] += h
__global__ void bn_apply_layer(const float* __restrict__ x, const float* __restrict__ gamma,
                               const float* __restrict__ beta, const int* __restrict__ batch,
                               float* __restrict__ out) {
    int r = blockIdx.x, c = threadIdx.x;
    float v = x[r * 128 + c];
    v = fmaf(gamma[c] * (v - g_mean[c]), g_rstd[c], beta[c]);
    v = fmaxf(v, 0.f);
    int bg = batch[r];
    v += g_vn[bg * 128 + c];
    out[r * 128 + c] = v;
    atomicAdd(&g_vt[bg * 128 + c], v);
}

// final conv BN apply (no relu, no vn): out -> buf0 and buf3 (h0)
__global__ void bn_apply_final(const float* __restrict__ x, const float* __restrict__ gamma,
                               const float* __restrict__ beta) {
    int r = blockIdx.x, c = threadIdx.x;
    float v = x[r * 128 + c];
    v = fmaf(gamma[c] * (v - g_mean[c]), g_rstd[c], beta[c]);
    g_buf0[r * 128 + c] = v;
    g_buf3[r * 128 + c] = v;
}

// small BN apply over NG rows. mode 0: x = relu(bn(x)); mode 1: vn += relu(bn(x))
__global__ void bn_apply_small(float* __restrict__ x, const float* __restrict__ gamma,
                               const float* __restrict__ beta, int C, int mode) {
    int r = blockIdx.x, c = threadIdx.x;
    float v = x[r * C + c];
    v = fmaf(gamma[c] * (v - g_mean[c]), g_rstd[c], beta[c]);
    v = fmaxf(v, 0.f);
    if (mode == 0) x[r * C + c] = v;
    else g_vn[r * C + c] += v;
}

// ---------------- small GEMM (per-graph rows): out[G x C] = in[G x K] @ W + bias ----------------
__global__ void gemm_small(const float* __restrict__ in, const float* __restrict__ W,
                           const float* __restrict__ bias, float* __restrict__ out,
                           int K, int C, const float* __restrict__ scale) {
    extern __shared__ float srow[];
    int g = blockIdx.x, c = threadIdx.x;
    float sc = scale ? (1.f / fmaxf(scale[g], 1.f)) : 1.f;
    for (int i = c; i < K; i += C) srow[i] = in[g * K + i] * sc;
    __syncthreads();
    float acc = bias[c];
    #pragma unroll 4
    for (int k = 0; k < K; k++) acc = fmaf(srow[k], W[k * C + c], acc);
    out[g * C + c] = acc;
}

__global__ void k_pool(const float* __restrict__ h, const int* __restrict__ batch) {
    int r = blockIdx.x, c = threadIdx.x;
    int bg = batch[r];
    atomicAdd(&g_pool[bg * 128 + c], h[r * 128 + c]);
    if (c == 0) atomicAdd(&g_cnt[bg], 1.f);
}

// ---------------- host orchestration ----------------
extern "C" void kernel_launch(void* const* d_in, const int* in_sizes, int n_in,
                              void* d_out, int out_size) {
    const float* x      = (const float*)d_in[0];
    const int*   ei     = (const int*)d_in[1];
    const int*   src    = ei;
    const int*   dst    = ei + N_EDGES;
    const int*   batch  = (const int*)d_in[2];
    const float* W      = (const float*)d_in[3];
    const float* b      = (const float*)d_in[4];
    const float* gamma  = (const float*)d_in[5];
    const float* beta   = (const float*)d_in[6];
    const float* vn_emb = (const float*)d_in[7];
    const float* W1     = (const float*)d_in[8];
    const float* b1     = (const float*)d_in[9];
    const float* g1     = (const float*)d_in[10];
    const float* bt1    = (const float*)d_in[11];
    const float* W2     = (const float*)d_in[12];
    const float* b2     = (const float*)d_in[13];
    const float* g2     = (const float*)d_in[14];
    const float* bt2    = (const float*)d_in[15];
    const float* Wout   = (const float*)d_in[16];
    const float* bout   = (const float*)d_in[17];
    float* out = (float*)d_out;

    float *buf0, *buf1, *buf2, *buf3, *vt, *z, *t, *pool, *cnt;
    cudaGetSymbolAddress((void**)&buf0, g_buf0);
    cudaGetSymbolAddress((void**)&buf1, g_buf1);
    cudaGetSymbolAddress((void**)&buf2, g_buf2);
    cudaGetSymbolAddress((void**)&buf3, g_buf3);
    cudaGetSymbolAddress((void**)&vt,   g_vt);
    cudaGetSymbolAddress((void**)&z,    g_z);
    cudaGetSymbolAddress((void**)&t,    g_t);
    cudaGetSymbolAddress((void**)&pool, g_pool);
    cudaGetSymbolAddress((void**)&cnt,  g_cnt);

    const int GEMM_SMEM = 128 * 128 * 4 + 64 * 16 * 4;  // 69632 bytes
    cudaFuncSetAttribute(gemm_big, cudaFuncAttributeMaxDynamicSharedMemorySize, GEMM_SMEM);

    // ---- build normalized CSR (every call; deterministic work) ----
    k_init<<<256, 256>>>(vn_emb);
    k_hist<<<(N_EDGES + 255) / 256, 256>>>(dst);
    k_dinv<<<(N_NODES + 255) / 256, 256>>>();
    k_scan<<<1, 1024>>>();
    k_fill<<<(N_EDGES + 255) / 256, 256>>>(src, dst);

    const int PROP_BLOCKS = (N_NODES * 32 + 255) / 256;
    const int GEMM_BLOCKS = (N_NODES + 63) / 64;

    const float* hcur = x;
    for (int i = 0; i < 2; i++) {
        int j = (i == 0) ? 1 : 0;  // torch negative-index wraparound
        k_prop<<<PROP_BLOCKS, 256>>>((const float4*)hcur, (float4*)buf1,
                                     (const float4*)hcur, 1.f, 0.f);
        gemm_big<<<GEMM_BLOCKS, 256, GEMM_SMEM>>>(buf1, W + i * 128 * 128, b + i * 128,
                                                  buf2, N_NODES);
        bn_zero<<<1, 512>>>();
        bn_stats<<<512, 128>>>(buf2, N_NODES, 128);
        bn_fin<<<1, 128>>>(1.f / N_NODES);
        vt_init<<<256, 256>>>();
        bn_apply_layer<<<N_NODES, 128>>>(buf2, gamma + i * 128, beta + i * 128, batch, buf0);
        hcur = buf0;

        // virtual-node MLP on vt [512 x 128]
        gemm_small<<<NG, 256, 128 * 4>>>(vt, W1 + j * 128 * 256, b1 + j * 256, z, 128, 256, nullptr);
        bn_zero<<<1, 512>>>();
        bn_stats<<<512, 256>>>(z, NG, 256);
        bn_fin<<<1, 256>>>(1.f / NG);
        bn_apply_small<<<NG, 256>>>(z, g1 + j * 256, bt1 + j * 256, 256, 0);

        gemm_small<<<NG, 128, 256 * 4>>>(z, W2 + j * 256 * 128, b2 + j * 128, t, 256, 128, nullptr);
        bn_zero<<<1, 512>>>();
        bn_stats<<<512, 128>>>(t, NG, 128);
        bn_fin<<<1, 128>>>(1.f / NG);
        bn_apply_small<<<NG, 128>>>(t, g2 + j * 128, bt2 + j * 128, 128, 1);  // vn += relu(bn(t))
    }

    // final conv + BN (no activation)
    k_prop<<<PROP_BLOCKS, 256>>>((const float4*)buf0, (float4*)buf1,
                                 (const float4*)buf0, 1.f, 0.f);
    gemm_big<<<GEMM_BLOCKS, 256, GEMM_SMEM>>>(buf1, W + 2 * 128 * 128, b + 2 * 128,
                                              buf2, N_NODES);
    bn_zero<<<1, 512>>>();
    bn_stats<<<512, 128>>>(buf2, N_NODES, 128);
    bn_fin<<<1, 128>>>(1.f / N_NODES);
    bn_apply_final<<<N_NODES, 128>>>(buf2, gamma + 2 * 128, beta + 2 * 128);

    // APPNP: h = 0.2 * A_hat h + 0.8 * h0, K=5 (ping-pong buf0 <-> buf1, h0 in buf3)
    const float* s = buf0;
    float* d = buf1;
    for (int k = 0; k < 5; k++) {
        k_prop<<<PROP_BLOCKS, 256>>>((const float4*)s, (float4*)d,
                                     (const float4*)buf3, 0.2f, 0.8f);
        const float* tmp = s; s = d; d = (float*)tmp;
    }

    // mean pool + head
    k_pool<<<N_NODES, 128>>>(s, batch);
    gemm_small<<<NG, 128, 128 * 4>>>(pool, Wout, bout, out, 128, 128, cnt);
}

// round 2
// speedup vs baseline: 1.3583x; 1.3583x over previous
#include <cuda_runtime.h>
#include <cuda_fp16.h>

#define N_NODES 50000
#define N_EDGES 600000
#define HID 128
#define NG 512
#define EPS 1e-5f
#define NBLK ((N_NODES + 1023) / 1024)   // 49

// ---------------- device scratch ----------------
__device__ float g_buf1[N_NODES * HID];   // prop fp32 output (gemm input)
__device__ float g_buf2[N_NODES * HID];   // gemm output (pre-BN)
__device__ uint2 g_ha[N_NODES * 32];      // half feature buffer A
__device__ uint2 g_hb[N_NODES * 32];      // half feature buffer B
__device__ uint2 g_h0[N_NODES * 32];      // half APPNP anchor
__device__ int   g_deg[N_NODES];
__device__ float g_dinv[N_NODES];
__device__ int   g_rowptr[N_NODES + 1];
__device__ int   g_cursor[N_NODES];
__device__ int   g_bsum[NBLK];
__device__ int   g_boff[NBLK];
__device__ int   g_csrc[N_EDGES];
__device__ float g_cw[N_EDGES];
__device__ float g_vn[NG * HID];
__device__ float g_vt[NG * HID];
__device__ float g_z[NG * 2 * HID];
__device__ float g_t[NG * HID];
__device__ float g_pool[NG * HID];
__device__ float g_cnt[NG];
__device__ float g_cs[8 * 512];           // per-BN-instance column sum/sumsq

// ---------------- half helpers ----------------
__device__ __forceinline__ float4 h2f4(uint2 u) {
    __half2 a = *(__half2*)&u.x, b = *(__half2*)&u.y;
    float2 fa = __half22float2(a), fb = __half22float2(b);
    return make_float4(fa.x, fa.y, fb.x, fb.y);
}
__device__ __forceinline__ uint2 f2h4(float4 v) {
    __half2 a = __floats2half2_rn(v.x, v.y), b = __floats2half2_rn(v.z, v.w);
    uint2 u;
    u.x = *(unsigned*)&a;
    u.y = *(unsigned*)&b;
    return u;
}

// ---------------- setup ----------------
__global__ void k_init(const float* __restrict__ vn_emb) {
    int i = blockIdx.x * blockDim.x + threadIdx.x;
    if (i < N_NODES) g_deg[i] = 0;
    if (i < NG * HID) { g_vn[i] = vn_emb[i & (HID - 1)]; g_pool[i] = 0.f; }
    if (i < 8 * 512) g_cs[i] = 0.f;
    if (i < NG) g_cnt[i] = 0.f;
}

__global__ void k_hist(const int* __restrict__ dst) {
    int e = blockIdx.x * blockDim.x + threadIdx.x;
    if (e < N_EDGES) atomicAdd(&g_deg[dst[e]], 1);
}

__global__ void k_dinv(const int* __restrict__ batch) {
    int i = blockIdx.x * blockDim.x + threadIdx.x;
    if (i < N_NODES) {
        g_dinv[i] = rsqrtf((float)(g_deg[i] + 1));
        atomicAdd(&g_cnt[batch[i]], 1.f);
    }
}

// scan stage 1: per-1024-chunk sums
__global__ void k_scan1() {
    __shared__ int ws[32];
    int tid = threadIdx.x;
    int i = blockIdx.x * 1024 + tid;
    int v = (i < N_NODES) ? g_deg[i] : 0;
    #pragma unroll
    for (int o = 16; o; o >>= 1) v += __shfl_down_sync(0xffffffffu, v, o);
    if ((tid & 31) == 0) ws[tid >> 5] = v;
    __syncthreads();
    if (tid < 32) {
        int t = ws[tid];
        #pragma unroll
        for (int o = 16; o; o >>= 1) t += __shfl_down_sync(0xffffffffu, t, o);
        if (tid == 0) g_bsum[blockIdx.x] = t;
    }
}

// scan stage 2: scan the 49 chunk sums
__global__ void k_scan2() {
    __shared__ int s[64];
    int t = threadIdx.x;
    int v = (t < NBLK) ? g_bsum[t] : 0;
    s[t] = v;
    __syncthreads();
    #pragma unroll
    for (int o = 1; o < 64; o <<= 1) {
        int u = (t >= o) ? s[t - o] : 0;
        __syncthreads();
        s[t] += u;
        __syncthreads();
    }
    if (t < NBLK) g_boff[t] = s[t] - v;
    if (t == NBLK - 1) g_rowptr[N_NODES] = s[t];
}

// scan stage 3: intra-chunk exclusive scan + chunk offset
__global__ void k_scan3() {
    __shared__ int wsum[32];
    int tid = threadIdx.x;
    int i = blockIdx.x * 1024 + tid;
    int v = (i < N_NODES) ? g_deg[i] : 0;
    int x = v;
    #pragma unroll
    for (int o = 1; o < 32; o <<= 1) {
        int y = __shfl_up_sync(0xffffffffu, x, o);
        if ((tid & 31) >= o) x += y;
    }
    if ((tid & 31) == 31) wsum[tid >> 5] = x;
    __syncthreads();
    if (tid < 32) {
        int s = wsum[tid];
        int z = s;
        #pragma unroll
        for (int o = 1; o < 32; o <<= 1) {
            int y = __shfl_up_sync(0xffffffffu, z, o);
            if (tid >= o) z += y;
        }
        wsum[tid] = z - s;
    }
    __syncthreads();
    int excl = g_boff[blockIdx.x] + (x - v) + wsum[tid >> 5];
    if (i < N_NODES) { g_rowptr[i] = excl; g_cursor[i] = excl; }
}

__global__ void k_fill(const int* __restrict__ src, const int* __restrict__ dst) {
    int e = blockIdx.x * blockDim.x + threadIdx.x;
    if (e >= N_EDGES) return;
    int d = dst[e], s = src[e];
    int pos = atomicAdd(&g_cursor[d], 1);
    g_csrc[pos] = s;
    g_cw[pos] = g_dinv[s] * g_dinv[d];
}

__global__ void k_tohalf(const float4* __restrict__ x, uint2* __restrict__ out) {
    int i = blockIdx.x * blockDim.x + threadIdx.x;
    if (i < N_NODES * 32) out[i] = f2h4(x[i]);
}

// ---------------- propagation (half gather) ----------------
__device__ __forceinline__ float4 gather(const uint2* __restrict__ in, int node, int lane) {
    float dv = g_dinv[node];
    float w0 = dv * dv;
    float4 p = h2f4(__ldg(&in[node * 32 + lane]));
    float4 acc = make_float4(w0 * p.x, w0 * p.y, w0 * p.z, w0 * p.w);
    int e = g_rowptr[node], end = g_rowptr[node + 1];
    for (; e + 1 < end; e += 2) {
        int s0 = __ldg(&g_csrc[e]);
        int s1 = __ldg(&g_csrc[e + 1]);
        float w0e = __ldg(&g_cw[e]);
        float w1e = __ldg(&g_cw[e + 1]);
        float4 q0 = h2f4(__ldg(&in[s0 * 32 + lane]));
        float4 q1 = h2f4(__ldg(&in[s1 * 32 + lane]));
        acc.x = fmaf(w0e, q0.x, acc.x); acc.y = fmaf(w0e, q0.y, acc.y);
        acc.z = fmaf(w0e, q0.z, acc.z); acc.w = fmaf(w0e, q0.w, acc.w);
        acc.x = fmaf(w1e, q1.x, acc.x); acc.y = fmaf(w1e, q1.y, acc.y);
        acc.z = fmaf(w1e, q1.z, acc.z); acc.w = fmaf(w1e, q1.w, acc.w);
    }
    if (e < end) {
        int s0 = __ldg(&g_csrc[e]);
        float w0e = __ldg(&g_cw[e]);
        float4 q0 = h2f4(__ldg(&in[s0 * 32 + lane]));
        acc.x = fmaf(w0e, q0.x, acc.x); acc.y = fmaf(w0e, q0.y, acc.y);
        acc.z = fmaf(w0e, q0.z, acc.z); acc.w = fmaf(w0e, q0.w, acc.w);
    }
    return acc;
}

// layer prop: fp32 output for GEMM
__global__ void k_prop_f(const uint2* __restrict__ in, float4* __restrict__ out) {
    int node = (blockIdx.x * blockDim.x + threadIdx.x) >> 5;
    if (node >= N_NODES) return;
    int lane = threadIdx.x & 31;
    out[node * 32 + lane] = gather(in, node, lane);
}

// APPNP prop: out = 0.2*agg + 0.8*h0, half output
__global__ void k_prop_ap(const uint2* __restrict__ in, const uint2* __restrict__ h0,
                          uint2* __restrict__ out) {
    int node = (blockIdx.x * blockDim.x + threadIdx.x) >> 5;
    if (node >= N_NODES) return;
    int lane = threadIdx.x & 31;
    float4 acc = gather(in, node, lane);
    float4 a0 = h2f4(__ldg(&h0[node * 32 + lane]));
    float4 o = make_float4(fmaf(0.2f, acc.x, 0.8f * a0.x), fmaf(0.2f, acc.y, 0.8f * a0.y),
                           fmaf(0.2f, acc.z, 0.8f * a0.z), fmaf(0.2f, acc.w, 0.8f * a0.w));
    out[node * 32 + lane] = f2h4(o);
}

// final APPNP prop fused with pooling atomics
__global__ void k_prop_pool(const uint2* __restrict__ in, const uint2* __restrict__ h0,
                            const int* __restrict__ batch) {
    int node = (blockIdx.x * blockDim.x + threadIdx.x) >> 5;
    if (node >= N_NODES) return;
    int lane = threadIdx.x & 31;
    float4 acc = gather(in, node, lane);
    float4 a0 = h2f4(__ldg(&h0[node * 32 + lane]));
    int base = batch[node] * 128 + lane * 4;
    atomicAdd(&g_pool[base + 0], fmaf(0.2f, acc.x, 0.8f * a0.x));
    atomicAdd(&g_pool[base + 1], fmaf(0.2f, acc.y, 0.8f * a0.y));
    atomicAdd(&g_pool[base + 2], fmaf(0.2f, acc.z, 0.8f * a0.z));
    atomicAdd(&g_pool[base + 3], fmaf(0.2f, acc.w, 0.8f * a0.w));
}

// ---------------- big GEMM, 128 rows/block, fused BN stats (+optional vt init) ----------------
__global__ void __launch_bounds__(512) gemm_big(
        const float* __restrict__ A, const float* __restrict__ Wg,
        const float* __restrict__ bias, float* __restrict__ C,
        float* __restrict__ cs, int do_vt) {
    extern __shared__ float sh[];
    float* Ws = sh;              // 128*128 = 16384 floats
    float* As = sh + 16384;      // 128*16  = 2048 floats
    int tid = threadIdx.x;
    for (int i = tid; i < 16384; i += 512) Ws[i] = Wg[i];
    if (do_vt && blockIdx.x == 0) {
        for (int i = tid; i < NG * HID; i += 512) g_vt[i] = g_vn[i];
    }
    int r0 = blockIdx.x * 128;
    int lane = tid & 31, w = tid >> 5;
    float4 acc[8];
    #pragma unroll
    for (int i = 0; i < 8; i++) acc[i] = make_float4(0.f, 0.f, 0.f, 0.f);

    int rr = tid >> 2, kk = (tid & 3) * 4;
    for (int k0 = 0; k0 < 128; k0 += 16) {
        __syncthreads();
        float4 av4 = (r0 + rr < N_NODES) ? *(const float4*)&A[(r0 + rr) * 128 + k0 + kk]
                                         : make_float4(0.f, 0.f, 0.f, 0.f);
        *(float4*)&As[rr * 16 + kk] = av4;
        __syncthreads();
        #pragma unroll
        for (int k = 0; k < 16; k++) {
            float4 wv = *(const float4*)&Ws[(k0 + k) * 128 + lane * 4];
            #pragma unroll
            for (int i = 0; i < 8; i++) {
                float av = As[(w * 8 + i) * 16 + k];
                acc[i].x = fmaf(av, wv.x, acc[i].x);
                acc[i].y = fmaf(av, wv.y, acc[i].y);
                acc[i].z = fmaf(av, wv.z, acc[i].z);
                acc[i].w = fmaf(av, wv.w, acc[i].w);
            }
        }
    }
    float4 bv = *(const float4*)&bias[lane * 4];
    float s0 = 0.f, s1 = 0.f, s2 = 0.f, s3 = 0.f;
    float q0 = 0.f, q1 = 0.f, q2 = 0.f, q3 = 0.f;
    #pragma unroll
    for (int i = 0; i < 8; i++) {
        int r = r0 + w * 8 + i;
        if (r < N_NODES) {
            float4 o = make_float4(acc[i].x + bv.x, acc[i].y + bv.y,
                                   acc[i].z + bv.z, acc[i].w + bv.w);
            *(float4*)&C[r * 128 + lane * 4] = o;
            s0 += o.x; s1 += o.y; s2 += o.z; s3 += o.w;
            q0 = fmaf(o.x, o.x, q0); q1 = fmaf(o.y, o.y, q1);
            q2 = fmaf(o.z, o.z, q2); q3 = fmaf(o.w, o.w, q3);
        }
    }
    // block-level column reduction into cs[0:128] (sum) and cs[128:256] (sumsq)
    __syncthreads();
    float* red = sh;  // 16 warps * 128 cols
    red[w * 128 + lane * 4 + 0] = s0; red[w * 128 + lane * 4 + 1] = s1;
    red[w * 128 + lane * 4 + 2] = s2; red[w * 128 + lane * 4 + 3] = s3;
    __syncthreads();
    if (tid < 128) {
        float t = 0.f;
        #pragma unroll
        for (int ww = 0; ww < 16; ww++) t += red[ww * 128 + tid];
        atomicAdd(&cs[tid], t);
    }
    __syncthreads();
    red[w * 128 + lane * 4 + 0] = q0; red[w * 128 + lane * 4 + 1] = q1;
    red[w * 128 + lane * 4 + 2] = q2; red[w * 128 + lane * 4 + 3] = q3;
    __syncthreads();
    if (tid < 128) {
        float t = 0.f;
        #pragma unroll
        for (int ww = 0; ww < 16; ww++) t += red[ww * 128 + tid];
        atomicAdd(&cs[128 + tid], t);
    }
}

// ---------------- BN apply (stats recomputed inline from cs) ----------------
// layer: h = relu(bn(x)) + vn[batch]; vt[batch] += h; write half
__global__ void bn_apply_layer(const float* __restrict__ x, const float* __restrict__ gamma,
                               const float* __restrict__ beta, const int* __restrict__ batch,
                               const float* __restrict__ cs, unsigned* __restrict__ out16) {
    int r = blockIdx.x, c = threadIdx.x;
    const float inv_n = 1.f / N_NODES;
    float m = cs[c] * inv_n;
    float rstd = rsqrtf(fmaf(-m, m, cs[128 + c] * inv_n) + EPS);
    float v = x[r * 128 + c];
    v = fmaf(gamma[c] * (v - m), rstd, beta[c]);
    v = fmaxf(v, 0.f);
    int bg = batch[r];
    v += g_vn[bg * 128 + c];
    atomicAdd(&g_vt[bg * 128 + c], v);
    float vo = __shfl_down_sync(0xffffffffu, v, 1);
    if ((c & 1) == 0) {
        __half2 h = __floats2half2_rn(v, vo);
        out16[r * 64 + (c >> 1)] = *(unsigned*)&h;
    }
}

// final: h = bn(x), no relu/vn; write to gather buffer AND anchor (half)
__global__ void bn_apply_final(const float* __restrict__ x, const float* __restrict__ gamma,
                               const float* __restrict__ beta, const float* __restrict__ cs,
                               unsigned* __restrict__ out16, unsigned* __restrict__ anchor16) {
    int r = blockIdx.x, c = threadIdx.x;
    const float inv_n = 1.f / N_NODES;
    float m = cs[c] * inv_n;
    float rstd = rsqrtf(fmaf(-m, m, cs[128 + c] * inv_n) + EPS);
    float v = x[r * 128 + c];
    v = fmaf(gamma[c] * (v - m), rstd, beta[c]);
    float vo = __shfl_down_sync(0xffffffffu, v, 1);
    if ((c & 1) == 0) {
        __half2 h = __floats2half2_rn(v, vo);
        unsigned u = *(unsigned*)&h;
        out16[r * 64 + (c >> 1)] = u;
        anchor16[r * 64 + (c >> 1)] = u;
    }
}

// small BN apply. mode 0: x = relu(bn(x)); mode 1: vn += relu(bn(x))
__global__ void bn_apply_small(float* __restrict__ x, const float* __restrict__ gamma,
                               const float* __restrict__ beta, const float* __restrict__ cs,
                               int C, int mode) {
    int r = blockIdx.x, c = threadIdx.x;
    const float inv_n = 1.f / NG;
    float m = cs[c] * inv_n;
    float rstd = rsqrtf(fmaf(-m, m, cs[C + c] * inv_n) + EPS);
    float v = x[r * C + c];
    v = fmaxf(fmaf(gamma[c] * (v - m), rstd, beta[c]), 0.f);
    if (mode == 0) x[r * C + c] = v;
    else g_vn[r * C + c] += v;
}

// ---------------- small GEMM with optional fused stats ----------------
__global__ void gemm_small(const float* __restrict__ in, const float* __restrict__ W,
                           const float* __restrict__ bias, float* __restrict__ out,
                           int K, int C, const float* __restrict__ scale,
                           float* __restrict__ cs) {
    extern __shared__ float srow[];
    int g = blockIdx.x, c = threadIdx.x;
    float sc = scale ? (1.f / fmaxf(scale[g], 1.f)) : 1.f;
    for (int i = c; i < K; i += C) srow[i] = in[g * K + i] * sc;
    __syncthreads();
    float acc = bias[c];
    #pragma unroll 4
    for (int k = 0; k < K; k++) acc = fmaf(srow[k], W[k * C + c], acc);
    out[g * C + c] = acc;
    if (cs) {
        atomicAdd(&cs[c], acc);
        atomicAdd(&cs[C + c], acc * acc);
    }
}

// ---------------- host orchestration ----------------
extern "C" void kernel_launch(void* const* d_in, const int* in_sizes, int n_in,
                              void* d_out, int out_size) {
    const float* x      = (const float*)d_in[0];
    const int*   ei     = (const int*)d_in[1];
    const int*   src    = ei;
    const int*   dst    = ei + N_EDGES;
    const int*   batch  = (const int*)d_in[2];
    const float* W      = (const float*)d_in[3];
    const float* b      = (const float*)d_in[4];
    const float* gamma  = (const float*)d_in[5];
    const float* beta   = (const float*)d_in[6];
    const float* vn_emb = (const float*)d_in[7];
    const float* W1     = (const float*)d_in[8];
    const float* b1     = (const float*)d_in[9];
    const float* g1     = (const float*)d_in[10];
    const float* bt1    = (const float*)d_in[11];
    const float* W2     = (const float*)d_in[12];
    const float* b2     = (const float*)d_in[13];
    const float* g2     = (const float*)d_in[14];
    const float* bt2    = (const float*)d_in[15];
    const float* Wout   = (const float*)d_in[16];
    const float* bout   = (const float*)d_in[17];
    float* out = (float*)d_out;

    float *buf1, *buf2, *vt, *z, *t, *pool, *cnt, *cs;
    uint2 *ha, *hb, *h0;
    cudaGetSymbolAddress((void**)&buf1, g_buf1);
    cudaGetSymbolAddress((void**)&buf2, g_buf2);
    cudaGetSymbolAddress((void**)&ha,   g_ha);
    cudaGetSymbolAddress((void**)&hb,   g_hb);
    cudaGetSymbolAddress((void**)&h0,   g_h0);
    cudaGetSymbolAddress((void**)&vt,   g_vt);
    cudaGetSymbolAddress((void**)&z,    g_z);
    cudaGetSymbolAddress((void**)&t,    g_t);
    cudaGetSymbolAddress((void**)&pool, g_pool);
    cudaGetSymbolAddress((void**)&cnt,  g_cnt);
    cudaGetSymbolAddress((void**)&cs,   g_cs);

    const int GEMM_SMEM = (16384 + 2048) * 4;  // 73728 bytes
    static int smem_set = 0;
    cudaFuncSetAttribute(gemm_big, cudaFuncAttributeMaxDynamicSharedMemorySize, GEMM_SMEM);
    (void)smem_set;

    // ---- CSR build ----
    k_init<<<256, 256>>>(vn_emb);
    k_hist<<<(N_EDGES + 255) / 256, 256>>>(dst);
    k_dinv<<<(N_NODES + 255) / 256, 256>>>(batch);
    k_scan1<<<NBLK, 1024>>>();
    k_scan2<<<1, 64>>>();
    k_scan3<<<NBLK, 1024>>>();
    k_fill<<<(N_EDGES + 255) / 256, 256>>>(src, dst);
    k_tohalf<<<(N_NODES * 32 + 255) / 256, 256>>>((const float4*)x, ha);

    const int PROP_BLOCKS = (N_NODES * 32 + 255) / 256;
    const int GEMM_BLOCKS = (N_NODES + 127) / 128;

    for (int i = 0; i < 2; i++) {
        int j = (i == 0) ? 1 : 0;  // torch negative-index wraparound
        float* csL = cs + i * 512;
        float* csZ = cs + (3 + i) * 512;
        float* csT = cs + (5 + i) * 512;

        k_prop_f<<<PROP_BLOCKS, 256>>>(ha, (float4*)buf1);
        gemm_big<<<GEMM_BLOCKS, 512, GEMM_SMEM>>>(buf1, W + i * 128 * 128, b + i * 128,
                                                  buf2, csL, 1);
        bn_apply_layer<<<N_NODES, 128>>>(buf2, gamma + i * 128, beta + i * 128, batch,
                                         csL, (unsigned*)ha);

        // virtual-node MLP on vt [512 x 128]
        gemm_small<<<NG, 256, 128 * 4>>>(vt, W1 + j * 128 * 256, b1 + j * 256, z,
                                         128, 256, nullptr, csZ);
        bn_apply_small<<<NG, 256>>>(z, g1 + j * 256, bt1 + j * 256, csZ, 256, 0);
        gemm_small<<<NG, 128, 256 * 4>>>(z, W2 + j * 256 * 128, b2 + j * 128, t,
                                         256, 128, nullptr, csT);
        bn_apply_small<<<NG, 128>>>(t, g2 + j * 128, bt2 + j * 128, csT, 128, 1);
    }

    // final conv + BN (no activation)
    k_prop_f<<<PROP_BLOCKS, 256>>>(ha, (float4*)buf1);
    gemm_big<<<GEMM_BLOCKS, 512, GEMM_SMEM>>>(buf1, W + 2 * 128 * 128, b + 2 * 128,
                                              buf2, cs + 2 * 512, 0);
    bn_apply_final<<<N_NODES, 128>>>(buf2, gamma + 2 * 128, beta + 2 * 128,
                                     cs + 2 * 512, (unsigned*)ha, (unsigned*)h0);

    // APPNP: 4 ping-pong props + final prop fused with pooling
    uint2* s = ha;
    uint2* d = hb;
    for (int k = 0; k < 4; k++) {
        k_prop_ap<<<PROP_BLOCKS, 256>>>(s, h0, d);
        uint2* tmp = s; s = d; d = tmp;
    }
    k_prop_pool<<<PROP_BLOCKS, 256>>>(s, h0, batch);

    // head: out = (pool / cnt) @ Wout + bout
    gemm_small<<<NG, 128, 128 * 4>>>(pool, Wout, bout, out, 128, 128, cnt, nullptr);
}